// round 5
// baseline (speedup 1.0000x reference)
#include <cuda_runtime.h>
#include <cuda_fp16.h>

#define T_STEPS 1024
#define N_INP   512
#define N_CELLS 4096
#define NBLK    128
#define NTHR    512            // 16 warps/block, 2 rows/warp -> 4096 rows
#define NWARP   16

// ---------------- scratch state (static device globals; no allocation) ----------------
__device__ float    g_Z[(size_t)T_STEPS * N_CELLS];            // precomputed Wz @ x_t, 16 MB
// interleaved fp16 weights: per row-pair rp (2048), per 8-col chunk j (512):
//   4 consecutive uint4 = [Wy_row0 | Wy_row1 | 256*Wx_row0 | 256*Wx_row1] halves 8j..8j+7
__device__ __half   g_Wc[(size_t)2 * N_CELLS * N_CELLS];       // 67 MB
__device__ float    g_y[2][N_CELLS];                           // exact fp32 state
__device__ unsigned g_yh[2][N_CELLS / 2];                      // half2 mirror of y (for dots)
__device__ float    g_S[T_STEPS + 1];                          // sum(relu(y_t)^2) per step
__device__ float    g_u[2];
__device__ float    g_w[2];
__device__ unsigned g_bar;                                     // grid barrier counter

// ---------------- init: reset state every call (determinism across graph replays) ----
__global__ void init_kernel() {
    int i = blockIdx.x * blockDim.x + threadIdx.x;
    if (i < N_CELLS) g_y[0][i] = 0.1f;
    if (i < N_CELLS / 2) {
        __half2 h = __float2half2_rn(0.1f);
        g_yh[0][i] = *(unsigned*)&h;
    }
    if (i <= T_STEPS) g_S[i] = (i == 0) ? 4096.0f * 0.01f : 0.0f;
    if (i == 0) { g_u[0] = 0.5f; g_w[0] = 1.0f; g_bar = 0u; }
}

// ---------------- fp32 -> fp16 interleaved weight conversion (once per call) ---------
// output uint4 id: s = id / (2048*512); rp = (id % (2048*512)) / 512; j = id % 512
// s in {0,1}: Wy row rp*2+s ; s in {2,3}: Wx row rp*2+(s-2) scaled by 256.
__global__ void convert_kernel(const float* __restrict__ Wy, const float* __restrict__ Wx) {
    const size_t NU4 = (size_t)2048 * 512 * 4;
    const size_t stride = (size_t)gridDim.x * blockDim.x;
    for (size_t id = (size_t)blockIdx.x * blockDim.x + threadIdx.x; id < NU4; id += stride) {
        const int s  = (int)(id >> 20);              // / (2048*512)
        const size_t rem = id & ((1u << 20) - 1);
        const int rp = (int)(rem >> 9);
        const int j  = (int)(rem & 511);
        const int row = rp * 2 + (s & 1);
        const float* src = ((s & 2) ? Wx : Wy) + (size_t)row * N_CELLS + j * 8;
        const float sc = (s & 2) ? 256.0f : 1.0f;
        float4 v0 = ((const float4*)src)[0];
        float4 v1 = ((const float4*)src)[1];
        __half2 h0 = __floats2half2_rn(v0.x * sc, v0.y * sc);
        __half2 h1 = __floats2half2_rn(v0.z * sc, v0.w * sc);
        __half2 h2 = __floats2half2_rn(v1.x * sc, v1.y * sc);
        __half2 h3 = __floats2half2_rn(v1.z * sc, v1.w * sc);
        uint4 o;
        o.x = *(unsigned*)&h0; o.y = *(unsigned*)&h1;
        o.z = *(unsigned*)&h2; o.w = *(unsigned*)&h3;
        ((uint4*)g_Wc)[(size_t)rp * 2048 + (size_t)j * 4 + s] = o;
    }
}

// ---------------- Z = X(T,K) @ Wz(N,K)^T : register-tiled fp32 GEMM ------------------
__global__ void zgemm_kernel(const float* __restrict__ X, const float* __restrict__ W) {
    __shared__ float Xs[16][64];
    __shared__ float Ws[16][64];
    const int tx = threadIdx.x;
    const int ty = threadIdx.y;
    const int tid = ty * 16 + tx;
    const int t0 = blockIdx.y * 64;
    const int n0 = blockIdx.x * 64;
    const int lrow = tid >> 2;
    const int lk   = (tid & 3) * 4;

    float acc[4][4];
    #pragma unroll
    for (int i = 0; i < 4; ++i)
        #pragma unroll
        for (int j = 0; j < 4; ++j) acc[i][j] = 0.f;

    for (int k0 = 0; k0 < N_INP; k0 += 16) {
        float4 xv = *(const float4*)(X + (size_t)(t0 + lrow) * N_INP + k0 + lk);
        float4 wv = *(const float4*)(W + (size_t)(n0 + lrow) * N_INP + k0 + lk);
        __syncthreads();
        Xs[lk + 0][lrow] = xv.x; Xs[lk + 1][lrow] = xv.y;
        Xs[lk + 2][lrow] = xv.z; Xs[lk + 3][lrow] = xv.w;
        Ws[lk + 0][lrow] = wv.x; Ws[lk + 1][lrow] = wv.y;
        Ws[lk + 2][lrow] = wv.z; Ws[lk + 3][lrow] = wv.w;
        __syncthreads();
        #pragma unroll
        for (int kk = 0; kk < 16; ++kk) {
            float xm[4], wn[4];
            #pragma unroll
            for (int i = 0; i < 4; ++i) xm[i] = Xs[kk][ty * 4 + i];
            #pragma unroll
            for (int j = 0; j < 4; ++j) wn[j] = Ws[kk][tx * 4 + j];
            #pragma unroll
            for (int i = 0; i < 4; ++i)
                #pragma unroll
                for (int j = 0; j < 4; ++j)
                    acc[i][j] = fmaf(xm[i], wn[j], acc[i][j]);
        }
    }
    #pragma unroll
    for (int i = 0; i < 4; ++i)
        #pragma unroll
        for (int j = 0; j < 4; ++j)
            g_Z[(size_t)(t0 + ty * 4 + i) * N_CELLS + (n0 + tx * 4 + j)] = acc[i][j];
}

// ---------------- persistent recurrence kernel: 1024 steps, 1 barrier/step ----------
// 16 warps/block, 2 rows/warp. HFMA2 hot loop, no F2F on weights/y.
__global__ void __launch_bounds__(NTHR) step_kernel(
    const float* __restrict__ a_shift, const float* __restrict__ b,
    float* __restrict__ out)
{
    __shared__ unsigned yp_h[N_CELLS / 2];   // relu(y_t) as half2, 8 KB
    __shared__ float sred[NWARP];            // per-warp sum(y_new+^2)
    __shared__ float sh_scal[4];             // [0]=w+, [1]=b+, [2]=a_t/256, [3]=1/(1+b+)

    const int tid  = threadIdx.x;
    const int wid  = tid >> 5;
    const int lane = tid & 31;
    const int gwid = blockIdx.x * NWARP + wid;       // row-pair id, 0..2047
    const int row0 = gwid * 2;

    const uint4* __restrict__ wp = ((const uint4*)g_Wc) + (size_t)gwid * 2048;
    const uint4* yph = (const uint4*)yp_h;

    float* out_us = out + (size_t)T_STEPS * N_CELLS;
    float* out_ws = out_us + T_STEPS;

    const __half2 hz = __float2half2_rn(0.0f);

    for (int t = 0; t < T_STEPS; ++t) {
        const int cur = t & 1;
        const int nxt = cur ^ 1;

        // ---- stage relu(y) as half2 into SMEM (no conversion: g_yh is fp16 mirror) ----
        {
            const uint4* src = (const uint4*)g_yh[cur];
            #pragma unroll
            for (int i = tid; i < N_CELLS / 8; i += NTHR) {      // 512 uint4
                uint4 v;
                v.x = __ldcg(&src[i].x); v.y = __ldcg(&src[i].y);
                v.z = __ldcg(&src[i].z); v.w = __ldcg(&src[i].w);
                __half2* h = (__half2*)&v;
                h[0] = __hmax2(h[0], hz);
                h[1] = __hmax2(h[1], hz);
                h[2] = __hmax2(h[2], hz);
                h[3] = __hmax2(h[3], hz);
                ((uint4*)yp_h)[i] = v;
            }
            if (tid == 0) {
                const float wcur = __ldcg(&g_w[cur]);
                const float bp   = fmaxf(b[t], 0.f);
                sh_scal[0] = fmaxf(wcur, 0.f);
                sh_scal[1] = bp;
                sh_scal[2] = a_shift[t] * (1.0f / 256.0f);   // undo Wx prescale
                sh_scal[3] = 1.0f / (1.0f + bp);
            }
        }
        __syncthreads();

        // ---- block 0: u & w scalar dynamics (S precomputed incrementally) ----
        if (blockIdx.x == 0 && tid == 0) {
            const float S  = __ldcg(&g_S[t]);
            const float u  = __ldcg(&g_u[cur]);
            const float w  = __ldcg(&g_w[cur]);
            const float bp = sh_scal[1];
            const float up = fminf(u, 1.f);
            const float wp = fmaxf(w, 0.f);
            const float r  = bp * 0.1f / (bp + up);
            const float du = 0.1f * (-u + u * (S + r * r));
            const float u_new   = u + du;
            const float du_plus = fmaxf(u_new, 0.f) - up;
            const float w_new   = w + 0.5f * (-w + wp * up + 1.f + du_plus);
            __stcg(&g_u[nxt], u_new);
            __stcg(&g_w[nxt], w_new);
            out_us[t] = u_new; out_ws[t] = w_new;
        }

        // ---- dual-row dual-matrix dots via HFMA2, fp32 window flush ----
        float aY0 = 0.f, aY1 = 0.f, aX0 = 0.f, aX1 = 0.f;
        #pragma unroll
        for (int jo = 0; jo < 4; ++jo) {
            __half2 hY0 = hz, hY1 = hz, hX0 = hz, hX1 = hz;
            #pragma unroll
            for (int ji = 0; ji < 4; ++ji) {
                const int j = (jo * 4 + ji) * 32 + lane;
                const uint4 yv = yph[j];
                const uint4 a0 = wp[(size_t)j * 4 + 0];
                const uint4 a1 = wp[(size_t)j * 4 + 1];
                const uint4 c0 = wp[(size_t)j * 4 + 2];
                const uint4 c1 = wp[(size_t)j * 4 + 3];
                const __half2* yh = (const __half2*)&yv;
                const __half2* pa0 = (const __half2*)&a0;
                const __half2* pa1 = (const __half2*)&a1;
                const __half2* pc0 = (const __half2*)&c0;
                const __half2* pc1 = (const __half2*)&c1;
                #pragma unroll
                for (int k = 0; k < 4; ++k) {
                    hY0 = __hfma2(pa0[k], yh[k], hY0);
                    hY1 = __hfma2(pa1[k], yh[k], hY1);
                    hX0 = __hfma2(pc0[k], yh[k], hX0);
                    hX1 = __hfma2(pc1[k], yh[k], hX1);
                }
            }
            float2 f;
            f = __half22float2(hY0); aY0 += f.x + f.y;
            f = __half22float2(hY1); aY1 += f.x + f.y;
            f = __half22float2(hX0); aX0 += f.x + f.y;
            f = __half22float2(hX1); aX1 += f.x + f.y;
        }
        #pragma unroll
        for (int o = 16; o > 0; o >>= 1) {
            aY0 += __shfl_xor_sync(0xffffffffu, aY0, o);
            aY1 += __shfl_xor_sync(0xffffffffu, aY1, o);
            aX0 += __shfl_xor_sync(0xffffffffu, aX0, o);
            aX1 += __shfl_xor_sync(0xffffffffu, aX1, o);
        }

        if (lane == 0) {
            const float wp_   = sh_scal[0];
            const float bp    = sh_scal[1];
            const float at    = sh_scal[2];      // already /256
            const float inv1b = sh_scal[3];
            const float zc    = bp * inv1b;
            const float yc    = inv1b / wp_;

            const float2 yold = *(const float2*)&g_y[cur][row0];
            const float2 z2   = *(const float2*)&g_Z[(size_t)t * N_CELLS + row0];

            const float yn0 = yold.x + 0.5f * (-yold.x + zc * z2.x + yc * aY0) + at * aX0;
            const float yn1 = yold.y + 0.5f * (-yold.y + zc * z2.y + yc * aY1) + at * aX1;

            __stcg((float2*)&g_y[nxt][row0], make_float2(yn0, yn1));
            __half2 hnew = __floats2half2_rn(yn0, yn1);
            __stcg(&g_yh[nxt][gwid], *(unsigned*)&hnew);

            const float r0p = fmaxf(yn0, 0.f), r1p = fmaxf(yn1, 0.f);
            *(float2*)&out[(size_t)t * N_CELLS + row0] = make_float2(r0p, r1p);
            sred[wid] = fmaf(r0p, r0p, r1p * r1p);
            __threadfence();   // release y/yh stores before barrier arrival
        }

        // ---- per-block S contribution for step t+1 ----
        __syncthreads();
        if (wid == 0) {
            float v = (lane < NWARP) ? sred[lane] : 0.f;
            #pragma unroll
            for (int o = 8; o > 0; o >>= 1) v += __shfl_xor_sync(0xffffffffu, v, o);
            if (lane == 0) atomicAdd(&g_S[t + 1], v);
        }

        // ---- grid barrier (monotone counter; reset by init_kernel each call) ----
        if (tid == 0) {
            __threadfence();
            atomicAdd(&g_bar, 1u);
            const unsigned target = (unsigned)(t + 1) * NBLK;
            while (*(volatile unsigned*)&g_bar < target) { }
            __threadfence();
        }
        __syncthreads();
    }
}

// ---------------- launch ------------------------------------------------------------
extern "C" void kernel_launch(void* const* d_in, const int* in_sizes, int n_in,
                              void* d_out, int out_size)
{
    const float* dir_input = (const float*)d_in[0];   // [T, N_IN]
    const float* a_shift   = (const float*)d_in[1];   // [T]
    const float* b         = (const float*)d_in[2];   // [T]
    const float* Wz        = (const float*)d_in[3];   // [N_CELLS, N_IN]
    const float* Wy        = (const float*)d_in[4];   // [N_CELLS, N_CELLS]
    const float* Wx        = (const float*)d_in[5];   // [N_CELLS, N_CELLS]
    float* out = (float*)d_out;                       // [T*N_CELLS] ys | [T] us | [T] ws

    (void)in_sizes; (void)n_in; (void)out_size;

    init_kernel<<<6, 1024>>>();
    convert_kernel<<<2048, 256>>>(Wy, Wx);

    dim3 gz(N_CELLS / 64, T_STEPS / 64);
    dim3 bz(16, 16);
    zgemm_kernel<<<gz, bz>>>(dir_input, Wz);

    step_kernel<<<NBLK, NTHR>>>(a_shift, b, out);
}